// round 5
// baseline (speedup 1.0000x reference)
#include <cuda_runtime.h>
#include <math.h>

#define T_ 6
#define N_ 20000
#define E_ 400000
#define F_ 64
#define C_ 64
#define H_ 128
#define BIG_ 0x3fffffff
#define KP_ 72   // padded feature channels: 64 x + 2 labels + zeros

// ---------------- scratch (device globals; no allocation) ----------------
__device__ __align__(128) int   g_lvl[T_][N_];
__device__ __align__(128) int   g_count[T_][N_];
__device__ __align__(128) int   g_rowptr[T_][N_ + 1];
__device__ __align__(128) int   g_cursor[T_][N_];
__device__ __align__(128) int   g_csrsrc[T_][E_];
__device__ __align__(128) float g_dinv[T_][N_];
__device__ __align__(128) float g_dxl[T_][N_ * KP_];  // dinv[n]*[x,labels,0pad]
__device__ __align__(128) float g_y[T_][N_ * KP_];    // aggregated features
__device__ __align__(128) float g_col[T_][N_];        // dinv*(h1 . W2[:,127])
__device__ unsigned long long   g_argmax[T_];
__device__ __align__(128) float g_seq[T_ * H_];

// ---------------- per-snapshot setup (batched over t = blockIdx.y) ----------------
__global__ void k_reset() {
    int t = blockIdx.y;
    int i = blockIdx.x * blockDim.x + threadIdx.x;
    if (i < N_) { g_lvl[t][i] = BIG_; g_count[t][i] = 0; }
    if (i == 0) g_argmax[t] = 0ULL;
}

__global__ void k_seed(const int* __restrict__ tgt) {
    int t = blockIdx.x;
    int i = threadIdx.x;
    if (i < C_) g_lvl[t][tgt[t * C_ + i]] = 0;
}

// Level-stamped BFS iteration k (see earlier rounds for the race argument).
__global__ void k_prop(const int* __restrict__ ei, int k) {
    int t = blockIdx.y;
    int i = blockIdx.x * blockDim.x + threadIdx.x;
    if (i >= E_) return;
    const int* src = ei + (size_t)t * 2 * E_;
    const int* dst = src + E_;
    int s = src[i], d = dst[i];
    int ls = g_lvl[t][s], ld = g_lvl[t][d];
    if (ls < k && ld > k) atomicMin(&g_lvl[t][d], k);
    if (ld < k && ls > k) atomicMin(&g_lvl[t][s], k);
}

__global__ void k_count(const int* __restrict__ ei) {
    int t = blockIdx.y;
    int i = blockIdx.x * blockDim.x + threadIdx.x;
    if (i >= E_) return;
    const int* src = ei + (size_t)t * 2 * E_;
    const int* dst = src + E_;
    int s = src[i], d = dst[i];
    if (g_lvl[t][s] < BIG_ && g_lvl[t][d] < BIG_) atomicAdd(&g_count[t][d], 1);
}

__global__ void k_scan() {
    int t = blockIdx.x;
    const int CH = 20;
    __shared__ int s[1024];
    int tid = threadIdx.x;
    int base = tid * CH;
    int loc[CH];
    int sum = 0;
#pragma unroll
    for (int i = 0; i < CH; i++) {
        int idx = base + i;
        int c = (idx < N_) ? g_count[t][idx] : 0;
        loc[i] = sum;
        sum += c;
    }
    s[tid] = sum;
    __syncthreads();
    for (int off = 1; off < 1024; off <<= 1) {
        int v = (tid >= off) ? s[tid - off] : 0;
        __syncthreads();
        s[tid] += v;
        __syncthreads();
    }
    int excl = s[tid] - sum;
#pragma unroll
    for (int i = 0; i < CH; i++) {
        int idx = base + i;
        if (idx < N_) {
            int o = excl + loc[i];
            g_rowptr[t][idx] = o;
            g_cursor[t][idx] = o;
            int lv = g_lvl[t][idx];
            g_dinv[t][idx] = (lv < BIG_) ? rsqrtf((float)g_count[t][idx] + 1.0f) : 0.0f;
        }
    }
    if (tid == 1023) g_rowptr[t][N_] = s[1023];
}

__global__ void k_fill(const int* __restrict__ ei) {
    int t = blockIdx.y;
    int i = blockIdx.x * blockDim.x + threadIdx.x;
    if (i >= E_) return;
    const int* src = ei + (size_t)t * 2 * E_;
    const int* dst = src + E_;
    int s = src[i], d = dst[i];
    if (g_lvl[t][s] < BIG_ && g_lvl[t][d] < BIG_) {
        int p = atomicAdd(&g_cursor[t][d], 1);
        g_csrsrc[t][p] = s;
    }
}

// ---------------- dxl[n] = dinv[n]*[x[n,0:64], is_c, other, 0...] ----------------
__global__ void __launch_bounds__(256) k_scale(const float* __restrict__ x) {
    int t = blockIdx.y;
    int e = blockIdx.x * 256 + threadIdx.x;
    const int NQ = KP_ / 4;  // 18 quads per node
    if (e >= N_ * NQ) return;
    int n = e / NQ;
    int q = e - n * NQ;
    float d = g_dinv[t][n];
    float4 v;
    if (q < 16) {
        float4 xv = *(const float4*)&x[((size_t)t * N_ + n) * F_ + q * 4];
        v = make_float4(d * xv.x, d * xv.y, d * xv.z, d * xv.w);
    } else if (q == 16) {
        int lv = g_lvl[t][n];
        v = make_float4(d * (lv == 0 ? 1.f : 0.f),
                        d * ((lv > 0 && lv < BIG_) ? 1.f : 0.f), 0.f, 0.f);
    } else {
        v = make_float4(0.f, 0.f, 0.f, 0.f);
    }
    *(float4*)&g_dxl[t][(size_t)n * KP_ + q * 4] = v;
}

// ---------------- y[d] = dinv[d]*(sum_{src->d} dxl[src] + dxl[d]) ----------------
// warp per row; lane l covers ch 2l..2l+1 (float2); lanes 0..3 also ch 64+2l..
__global__ void __launch_bounds__(256) k_agg() {
    int t = blockIdx.y;
    int tid = threadIdx.x;
    int warp = tid >> 5, lane = tid & 31;
    int row = blockIdx.x * 8 + warp;
    if (row >= N_) return;
    int s0 = g_rowptr[t][row], s1 = g_rowptr[t][row + 1];
    const int* __restrict__ csr = g_csrsrc[t];
    const float* __restrict__ dxl = g_dxl[t];
    bool ex = lane < 4;
    int mo = 2 * lane;
    int eo = 64 + 2 * lane;

    float2 m0 = {0.f, 0.f}, m1 = {0.f, 0.f}, m2 = {0.f, 0.f}, m3 = {0.f, 0.f};
    float2 e0 = {0.f, 0.f}, e1 = {0.f, 0.f};
    int j = s0;
    for (; j + 4 <= s1; j += 4) {
        size_t p0 = (size_t)csr[j] * KP_, p1 = (size_t)csr[j + 1] * KP_;
        size_t p2 = (size_t)csr[j + 2] * KP_, p3 = (size_t)csr[j + 3] * KP_;
        float2 v0 = *(const float2*)&dxl[p0 + mo];
        float2 v1 = *(const float2*)&dxl[p1 + mo];
        float2 v2 = *(const float2*)&dxl[p2 + mo];
        float2 v3 = *(const float2*)&dxl[p3 + mo];
        m0.x += v0.x; m0.y += v0.y; m1.x += v1.x; m1.y += v1.y;
        m2.x += v2.x; m2.y += v2.y; m3.x += v3.x; m3.y += v3.y;
        if (ex) {
            float2 w0 = *(const float2*)&dxl[p0 + eo];
            float2 w1 = *(const float2*)&dxl[p1 + eo];
            float2 w2 = *(const float2*)&dxl[p2 + eo];
            float2 w3 = *(const float2*)&dxl[p3 + eo];
            e0.x += w0.x + w1.x; e0.y += w0.y + w1.y;
            e1.x += w2.x + w3.x; e1.y += w2.y + w3.y;
        }
    }
    for (; j < s1; j++) {
        size_t p = (size_t)csr[j] * KP_;
        float2 v = *(const float2*)&dxl[p + mo];
        m0.x += v.x; m0.y += v.y;
        if (ex) {
            float2 w = *(const float2*)&dxl[p + eo];
            e0.x += w.x; e0.y += w.y;
        }
    }
    size_t ps = (size_t)row * KP_;
    float2 sv = *(const float2*)&dxl[ps + mo];
    float d = g_dinv[t][row];
    float2 om;
    om.x = d * ((m0.x + m1.x) + (m2.x + m3.x) + sv.x);
    om.y = d * ((m0.y + m1.y) + (m2.y + m3.y) + sv.y);
    *(float2*)&g_y[t][ps + mo] = om;
    if (ex) {
        float2 se = *(const float2*)&dxl[ps + eo];
        float2 oe;
        oe.x = d * (e0.x + e1.x + se.x);
        oe.y = d * (e0.y + e1.y + se.y);
        *(float2*)&g_y[t][ps + eo] = oe;
    }
}

__device__ __forceinline__ float warp_sum(float v) {
    v += __shfl_down_sync(0xffffffffu, v, 16);
    v += __shfl_down_sync(0xffffffffu, v, 8);
    v += __shfl_down_sync(0xffffffffu, v, 4);
    v += __shfl_down_sync(0xffffffffu, v, 2);
    v += __shfl_down_sync(0xffffffffu, v, 1);
    return v;
}

// ---------------- fused GEMM: h1 = relu(y@W1+b1) in regs; g_col epilogue ----------------
#define BM 64
#define KC 36
__global__ void __launch_bounds__(256) k_gemm(const float* __restrict__ W1,
                                              const float* __restrict__ b1,
                                              const float* __restrict__ W2) {
    int t = blockIdx.y;
    const float* A = g_y[t];
    __shared__ float As[KC][BM + 4];
    __shared__ float Bs[KC][H_];
    __shared__ float w2cs[H_];
    int tid = threadIdx.x;
    int tc = tid & 31;
    int tr = tid >> 5;
    int m0 = blockIdx.x * BM;
    if (tid < H_) w2cs[tid] = W2[(size_t)tid * H_ + (H_ - 1)];

    float acc[8][4];
#pragma unroll
    for (int i = 0; i < 8; i++)
#pragma unroll
        for (int j = 0; j < 4; j++) acc[i][j] = 0.0f;

    for (int kb = 0; kb < KP_; kb += KC) {
        // A tile: 64 rows x 36 cols = 576 quads
#pragma unroll
        for (int i = 0; i < 3; i++) {
            int e = tid + i * 256;
            if (e < 64 * (KC / 4)) {
                int r = e / (KC / 4);
                int kq = (e - r * (KC / 4)) * 4;
                int gr = m0 + r;
                float4 v = make_float4(0.f, 0.f, 0.f, 0.f);
                if (gr < N_) v = *(const float4*)&A[(size_t)gr * KP_ + kb + kq];
                As[kq + 0][r] = v.x;
                As[kq + 1][r] = v.y;
                As[kq + 2][r] = v.z;
                As[kq + 3][r] = v.w;
            }
        }
        // W tile: 36 x 128 = 1152 quads (rows >= 67 are zero)
#pragma unroll
        for (int i = 0; i < 5; i++) {
            int e = tid + i * 256;
            if (e < KC * 32) {
                int kr = e >> 5;
                int cq = (e & 31) * 4;
                int grow = kb + kr;
                float4 v = make_float4(0.f, 0.f, 0.f, 0.f);
                if (grow < F_ + 3) v = *(const float4*)&W1[(size_t)grow * H_ + cq];
                *(float4*)&Bs[kr][cq] = v;
            }
        }
        __syncthreads();
#pragma unroll
        for (int k = 0; k < KC; k++) {
            float4 b = *(float4*)&Bs[k][tc * 4];
            float4 al = *(float4*)&As[k][tr * 8];
            float4 ah = *(float4*)&As[k][tr * 8 + 4];
            float a[8] = {al.x, al.y, al.z, al.w, ah.x, ah.y, ah.z, ah.w};
#pragma unroll
            for (int i = 0; i < 8; i++) {
                acc[i][0] = fmaf(a[i], b.x, acc[i][0]);
                acc[i][1] = fmaf(a[i], b.y, acc[i][1]);
                acc[i][2] = fmaf(a[i], b.z, acc[i][2]);
                acc[i][3] = fmaf(a[i], b.w, acc[i][3]);
            }
        }
        __syncthreads();
    }

    float4 bb = *(const float4*)&b1[tc * 4];
    float w0 = w2cs[tc * 4], w1v = w2cs[tc * 4 + 1], w2v = w2cs[tc * 4 + 2], w3 = w2cs[tc * 4 + 3];
#pragma unroll
    for (int i = 0; i < 8; i++) {
        int r = m0 + tr * 8 + i;
        if (r >= N_) break;
        float h0 = fmaxf(acc[i][0] + bb.x, 0.f);
        float h1 = fmaxf(acc[i][1] + bb.y, 0.f);
        float h2 = fmaxf(acc[i][2] + bb.z, 0.f);
        float h3 = fmaxf(acc[i][3] + bb.w, 0.f);
        float dot = h0 * w0 + h1 * w1v + h2 * w2v + h3 * w3;
        dot = warp_sum(dot);
        if (tc == 0) g_col[t][r] = g_dinv[t][r] * dot;
    }
}

// ---------------- layer-2 scalar aggregation + fused argmax ----------------
__global__ void __launch_bounds__(256) k_col_argmax(const float* __restrict__ b2) {
    int t = blockIdx.y;
    int tid = threadIdx.x;
    int warp = tid >> 5, lane = tid & 31;
    int row = blockIdx.x * 8 + warp;
    unsigned long long p = 0ULL;
    float b = b2[H_ - 1];
    if (row < N_) {
        int s0 = g_rowptr[t][row], s1 = g_rowptr[t][row + 1];
        const int* __restrict__ csr = g_csrsrc[t];
        float s = 0.f;
        for (int j = s0 + lane; j < s1; j += 32) s += g_col[t][csr[j]];
        s = warp_sum(s);
        if (lane == 0) {
            float d = g_dinv[t][row];
            if (d > 0.f) {
                float v = fmaxf(fmaf(d, s + g_col[t][row], b), 0.f);
                p = ((unsigned long long)__float_as_uint(v) << 32) |
                    (unsigned int)(0x7fffffff - row);
            }
        }
    }
    __shared__ unsigned long long sm[8];
    if (lane == 0) sm[warp] = p;
    __syncthreads();
    if (tid == 0) {
        unsigned long long m = sm[0];
#pragma unroll
        for (int i = 1; i < 8; i++) m = (sm[i] > m) ? sm[i] : m;
        if (m) atomicMax(&g_argmax[t], m);
    }
}

// ---------------- recompute h1 on top's neighborhood; h2[top,:] -> g_seq ----------------
__global__ void __launch_bounds__(128) k_top(const float* __restrict__ W1,
                                             const float* __restrict__ b1,
                                             const float* __restrict__ W2,
                                             const float* __restrict__ b2) {
    int t = blockIdx.x;
    int top = 0x7fffffff - (int)(g_argmax[t] & 0x7fffffffULL);
    int c = threadIdx.x;
    __shared__ float yrow[KP_];
    __shared__ float svec[H_];

    int s0 = g_rowptr[t][top], s1 = g_rowptr[t][top + 1];
    float sv = 0.f;
    float bc = b1[c];
    for (int idx = -1; idx < s1 - s0; idx++) {
        int u = (idx < 0) ? top : g_csrsrc[t][s0 + idx];
        __syncthreads();
        if (c < KP_) yrow[c] = g_y[t][(size_t)u * KP_ + c];
        __syncthreads();
        float h = bc;
#pragma unroll 4
        for (int k = 0; k < F_ + 3; k++) h = fmaf(yrow[k], W1[(size_t)k * H_ + c], h);
        sv += g_dinv[t][u] * fmaxf(h, 0.f);
    }
    svec[c] = sv;
    __syncthreads();
    float o = 0.f;
#pragma unroll 4
    for (int k = 0; k < H_; k++) o = fmaf(svec[k], W2[(size_t)k * H_ + c], o);
    float dtop = g_dinv[t][top];
    g_seq[t * H_ + c] = fmaxf(fmaf(dtop, o, b2[c]), 0.f);
}

// ---------------- GRU + MLP head ----------------
__global__ void __launch_bounds__(128) k_final(const float* __restrict__ Wih,
                                               const float* __restrict__ Whh,
                                               const float* __restrict__ bih,
                                               const float* __restrict__ bhh,
                                               const float* __restrict__ Wc1,
                                               const float* __restrict__ bc1,
                                               const float* __restrict__ Wc2,
                                               const float* __restrict__ bc2,
                                               float* __restrict__ out) {
    __shared__ float h[H_], xt[H_], sgi[3 * H_], sgh[3 * H_], hid[H_ / 2];
    int tid = threadIdx.x, lane = tid & 31, w = tid >> 5;
    h[tid] = 0.0f;
    __syncthreads();
    for (int t = 0; t < T_; t++) {
        xt[tid] = g_seq[t * H_ + tid];
        __syncthreads();
        for (int o = w; o < 3 * H_; o += 4) {
            float si = 0.f, sh = 0.f;
            for (int k = lane; k < H_; k += 32) {
                si += xt[k] * Wih[(size_t)o * H_ + k];
                sh += h[k] * Whh[(size_t)o * H_ + k];
            }
            si = warp_sum(si);
            sh = warp_sum(sh);
            if (lane == 0) {
                sgi[o] = si + bih[o];
                sgh[o] = sh + bhh[o];
            }
        }
        __syncthreads();
        float r = 1.0f / (1.0f + expf(-(sgi[tid] + sgh[tid])));
        float z = 1.0f / (1.0f + expf(-(sgi[tid + H_] + sgh[tid + H_])));
        float n = tanhf(sgi[tid + 2 * H_] + r * sgh[tid + 2 * H_]);
        float hn = (1.0f - z) * n + z * h[tid];
        __syncthreads();
        h[tid] = hn;
        __syncthreads();
    }
    if (tid < H_ / 2) {
        float s = bc1[tid];
        for (int k = 0; k < H_; k++) s += h[k] * Wc1[(size_t)k * (H_ / 2) + tid];
        hid[tid] = fmaxf(s, 0.0f);
    }
    __syncthreads();
    if (tid == 0) {
        float s = bc2[0];
        for (int j = 0; j < H_ / 2; j++) s += hid[j] * Wc2[j];
        out[0] = 1.0f / (1.0f + expf(-s));
    }
}

// ---------------- launch ----------------
extern "C" void kernel_launch(void* const* d_in, const int* in_sizes, int n_in,
                              void* d_out, int out_size) {
    const float* x   = (const float*)d_in[0];
    const int*   ei  = (const int*)d_in[1];
    const int*   tgt = (const int*)d_in[2];
    const float* W1  = (const float*)d_in[3];
    const float* b1  = (const float*)d_in[4];
    const float* W2  = (const float*)d_in[5];
    const float* b2  = (const float*)d_in[6];
    const float* Wih = (const float*)d_in[7];
    const float* Whh = (const float*)d_in[8];
    const float* bih = (const float*)d_in[9];
    const float* bhh = (const float*)d_in[10];
    const float* Wc1 = (const float*)d_in[11];
    const float* bc1 = (const float*)d_in[12];
    const float* Wc2 = (const float*)d_in[13];
    const float* bc2 = (const float*)d_in[14];
    float* out = (float*)d_out;

    const dim3 GN((N_ + 255) / 256, T_);
    const dim3 GE((E_ + 255) / 256, T_);
    const dim3 GM((N_ + BM - 1) / BM, T_);
    const dim3 GR((N_ + 7) / 8, T_);
    const dim3 GS((N_ * (KP_ / 4) + 255) / 256, T_);

    k_reset<<<GN, 256>>>();
    k_seed<<<T_, 64>>>(tgt);
    k_prop<<<GE, 256>>>(ei, 1);
    k_prop<<<GE, 256>>>(ei, 2);
    k_count<<<GE, 256>>>(ei);
    k_scan<<<T_, 1024>>>();
    k_fill<<<GE, 256>>>(ei);

    k_scale<<<GS, 256>>>(x);                 // dxl = dinv*[x,labels]
    k_agg<<<GR, 256>>>();                    // y = dinv*(sum dxl[src] + dxl[self])
    k_gemm<<<GM, 256>>>(W1, b1, W2);         // h1 in regs -> g_col only
    k_col_argmax<<<GR, 256>>>(b2);           // layer-2 scalar agg + argmax
    k_top<<<T_, 128>>>(W1, b1, W2, b2);      // recompute h1 on top's nbhd -> g_seq
    k_final<<<1, 128>>>(Wih, Whh, bih, bhh, Wc1, bc1, Wc2, bc2, out);
}